// round 2
// baseline (speedup 1.0000x reference)
#include <cuda_runtime.h>
#include <math.h>

#define MM 4096
#define DD 2048

// Scratch (allocation-free rule: __device__ globals)
__device__ float g_qt[MM];
__device__ float g_kt[MM];
__device__ float g_vt[MM];
__device__ float g_scal[8]; // 0:it 1:ft 2:ot 3:denom 4:k.qt

// ---------------------------------------------------------------------------
// K1: row-dot GEMVs. Blocks 0..M-1 -> qt, M..2M-1 -> kt (scaled by 1/64),
// 2M..3M-1 -> vt, 3M..3M+2 -> gate scalars (exp/exp/sigmoid applied).
// 256 threads/block; all loads front-batched for MLP before any FMA.
// ---------------------------------------------------------------------------
__global__ void __launch_bounds__(256) k1_gemv(
    const float* __restrict__ x,
    const float* __restrict__ Wq, const float* __restrict__ bq,
    const float* __restrict__ Wk, const float* __restrict__ bk,
    const float* __restrict__ Wv, const float* __restrict__ bV,
    const float* __restrict__ Wi, const float* __restrict__ bi,
    const float* __restrict__ Wf, const float* __restrict__ bf,
    const float* __restrict__ Wo, const float* __restrict__ bo)
{
    int blk = blockIdx.x;
    const float* W;
    float bias;
    int mode, row;
    if (blk < MM)          { row = blk;        W = Wq + (size_t)row * DD; bias = bq[row]; mode = 0; }
    else if (blk < 2 * MM) { row = blk -   MM; W = Wk + (size_t)row * DD; bias = bk[row]; mode = 1; }
    else if (blk < 3 * MM) { row = blk - 2*MM; W = Wv + (size_t)row * DD; bias = bV[row]; mode = 2; }
    else {
        int s = blk - 3 * MM;
        mode = 3 + s; row = 0;
        W    = (s == 0) ? Wi    : ((s == 1) ? Wf    : Wo);
        bias = (s == 0) ? bi[0] : ((s == 1) ? bf[0] : bo[0]);
    }

    int t = threadIdx.x;
    const float4* W4 = (const float4*)W;
    const float4* x4 = (const float4*)x;

    // Front-batch all 4 loads (2 weight + 2 x float4s) before any math.
    float4 w0 = W4[t];
    float4 w1 = W4[t + 256];
    float4 x0 = x4[t];
    float4 x1 = x4[t + 256];

    float acc = w0.x * x0.x + w0.y * x0.y + w0.z * x0.z + w0.w * x0.w
              + w1.x * x1.x + w1.y * x1.y + w1.z * x1.z + w1.w * x1.w;

#pragma unroll
    for (int o = 16; o > 0; o >>= 1) acc += __shfl_down_sync(0xffffffffu, acc, o);

    __shared__ float ws[8];
    if ((t & 31) == 0) ws[t >> 5] = acc;
    __syncthreads();

    if (t == 0) {
        float s = bias;
#pragma unroll
        for (int w = 0; w < 8; w++) s += ws[w];
        if      (mode == 0) g_qt[row] = s;
        else if (mode == 1) g_kt[row] = s * (1.0f / 64.0f);   // 1/sqrt(4096)
        else if (mode == 2) g_vt[row] = s;
        else if (mode == 3) g_scal[0] = expf(s);              // it
        else if (mode == 4) g_scal[1] = expf(s);              // ft
        else                g_scal[2] = 1.0f / (1.0f + expf(-s)); // ot
    }
}

// ---------------------------------------------------------------------------
// K2: single block. k.qt and n_prev.qt dots -> denom; writes n output.
// ---------------------------------------------------------------------------
__global__ void __launch_bounds__(512) k2_small(
    const float* __restrict__ n_prev, float* __restrict__ out)
{
    int t = threadIdx.x;
    float skq = 0.f, snq = 0.f;
#pragma unroll
    for (int c = 0; c < 8; c++) {
        int i = t + c * 512;
        float q = g_qt[i];
        skq += g_kt[i] * q;
        snq += n_prev[i] * q;
    }
#pragma unroll
    for (int o = 16; o > 0; o >>= 1) {
        skq += __shfl_down_sync(0xffffffffu, skq, o);
        snq += __shfl_down_sync(0xffffffffu, snq, o);
    }
    __shared__ float s1[16], s2[16];
    if ((t & 31) == 0) { s1[t >> 5] = skq; s2[t >> 5] = snq; }
    __syncthreads();

    float it = g_scal[0], ft = g_scal[1];
    if (t == 0) {
        float a = 0.f, b = 0.f;
#pragma unroll
        for (int w = 0; w < 16; w++) { a += s1[w]; b += s2[w]; }
        float nq = ft * b + it * a;          // n^T qt = ft*(n_prev.qt) + it*(k.qt)
        g_scal[3] = fmaxf(fabsf(nq), 1.0f);  // denom
        g_scal[4] = a;                       // k.qt
    }

    // n = ft*n_prev + it*kt  -> out[M + M*M .. ]
    float* n_out = out + MM + (size_t)MM * MM;
#pragma unroll
    for (int c = 0; c < 8; c++) {
        int i = t + c * 512;
        n_out[i] = ft * n_prev[i] + it * g_kt[i];
    }
}

// ---------------------------------------------------------------------------
// K3: one block per cp row. Writes C row, fuses cp-row.qt dot, emits ht[row].
//   C[i,j]   = ft*cp[i,j] + (it*v[i])*k[j]
//   ht[i]    = ot * (ft*(cp_row.qt) + it*v[i]*(k.qt)) / denom
// All 4 cp loads front-batched (MLP_p1=4) before any store/dot.
// ---------------------------------------------------------------------------
__global__ void __launch_bounds__(256) k3_update(
    const float* __restrict__ cp, float* __restrict__ out)
{
    int row = blockIdx.x;
    int t = threadIdx.x;

    float it = g_scal[0], ft = g_scal[1], ot = g_scal[2];
    float denom = g_scal[3], skq = g_scal[4];
    float a = it * g_vt[row];

    const float4* cp4 = (const float4*)(cp  + (size_t)row * MM);
    float4*       C4  = (float4*)(out + MM + (size_t)row * MM);
    const float4* q4  = (const float4*)g_qt;
    const float4* k4  = (const float4*)g_kt;

    // Front-batch the entire 16KB row read: 4 independent float4 loads in
    // flight per thread before any dependent math/stores.
    float4 cv[4], kv[4], qv[4];
#pragma unroll
    for (int c = 0; c < 4; c++) cv[c] = cp4[t + c * 256];
#pragma unroll
    for (int c = 0; c < 4; c++) kv[c] = k4[t + c * 256];
#pragma unroll
    for (int c = 0; c < 4; c++) qv[c] = q4[t + c * 256];

    float y = 0.f;
#pragma unroll
    for (int c = 0; c < 4; c++) {
        float4 o;
        o.x = ft * cv[c].x + a * kv[c].x;
        o.y = ft * cv[c].y + a * kv[c].y;
        o.z = ft * cv[c].z + a * kv[c].z;
        o.w = ft * cv[c].w + a * kv[c].w;
        C4[t + c * 256] = o;
        y += cv[c].x * qv[c].x + cv[c].y * qv[c].y
           + cv[c].z * qv[c].z + cv[c].w * qv[c].w;
    }

#pragma unroll
    for (int o2 = 16; o2 > 0; o2 >>= 1) y += __shfl_down_sync(0xffffffffu, y, o2);

    __shared__ float ws[8];
    if ((t & 31) == 0) ws[t >> 5] = y;
    __syncthreads();

    if (t == 0) {
        float s = 0.f;
#pragma unroll
        for (int w = 0; w < 8; w++) s += ws[w];
        float h = (ft * s + a * skq) / denom;
        out[row] = ot * h;                   // ht
    }
}

// ---------------------------------------------------------------------------
// Inputs (metadata order): x, cp, n_prev, Wq, bq, Wk, bk, Wv, bV,
//                          Wi, bi, Wf, bf, Wo, bo
// Output: ht (M) | C (M*M) | n (M), fp32
// ---------------------------------------------------------------------------
extern "C" void kernel_launch(void* const* d_in, const int* in_sizes, int n_in,
                              void* d_out, int out_size)
{
    const float* x      = (const float*)d_in[0];
    const float* cp     = (const float*)d_in[1];
    const float* n_prev = (const float*)d_in[2];
    const float* Wq     = (const float*)d_in[3];
    const float* bq     = (const float*)d_in[4];
    const float* Wk     = (const float*)d_in[5];
    const float* bk     = (const float*)d_in[6];
    const float* Wv     = (const float*)d_in[7];
    const float* bV     = (const float*)d_in[8];
    const float* bi_    = (const float*)d_in[10];
    const float* Wi     = (const float*)d_in[9];
    const float* Wf     = (const float*)d_in[11];
    const float* bf_    = (const float*)d_in[12];
    const float* Wo     = (const float*)d_in[13];
    const float* bo_    = (const float*)d_in[14];
    float* out = (float*)d_out;

    k1_gemv<<<3 * MM + 3, 256>>>(x, Wq, bq, Wk, bk, Wv, bV, Wi, bi_, Wf, bf_, Wo, bo_);
    k2_small<<<1, 512>>>(n_prev, out);
    k3_update<<<MM, 256>>>(cp, out);
}